// round 9
// baseline (speedup 1.0000x reference)
#include <cuda_runtime.h>
#include <cuda_bf16.h>

#define DIM        128
#define MAX_ENT    50048
#define MAX_REL    24
#define MAX_NEEDED 4096
#define GROUPS     8
#define EPT        16            // edges per thread in the scan

// ---------------- device scratch (static zero-init == "clean" state) ------
// g_slot[node]: 0 = free, 1 = being claimed, s+2 = assigned slot s
__device__ int          g_is64;
__device__ int          g_slot[MAX_ENT];
__device__ unsigned int g_bits[MAX_ENT / 32];        // membership bitmap
__device__ int          g_needed_nodes[MAX_NEEDED];
__device__ int          g_n_needed;
__device__ float        g_msg[(size_t)MAX_NEEDED * MAX_REL * DIM];
__device__ float        g_cnt[MAX_NEEDED * MAX_REL];
__device__ float        g_agg[MAX_NEEDED * DIM];
__device__ unsigned int g_cntB, g_senseB;            // sense-reversal barrier

__device__ __forceinline__ int ld_idx(const void* p, size_t i, int is64) {
    if (is64) return (int)((const long long*)p)[i];
    return ((const int*)p)[i];
}

// fast tanh: 1 - 2/(e^{2x}+1); rel err ~1e-7
__device__ __forceinline__ float ftanh(float x) {
    float e = __expf(2.0f * x);
    return 1.0f - 2.0f / (e + 1.0f);
}

// Sense-reversal grid barrier; self-resetting (graph-replay safe). All blocks
// of the calling kernel are co-resident, so spinning cannot deadlock.
__device__ __forceinline__ void barrier_sr(unsigned int* cnt,
                                           unsigned int* sense,
                                           unsigned int nblk) {
    __threadfence();
    __syncthreads();
    if (threadIdx.x == 0) {
        unsigned int my_sense = *(volatile unsigned int*)sense;
        unsigned int v = atomicAdd(cnt, 1u);
        if (v == nblk - 1u) {
            atomicExch(cnt, 0u);
            __threadfence();
            atomicExch(sense, my_sense ^ 1u);
        } else {
            while (*(volatile unsigned int*)sense == my_sense) { }
        }
        __threadfence();
    }
    __syncthreads();
}

// ============ 1) k_mark: dtype detect + mark + compact =====================
__global__ void k_mark(const unsigned int* __restrict__ ei_words,
                       const void* __restrict__ sample, int batch) {
    __shared__ int s_any;
    if (threadIdx.x == 0) s_any = 0;
    __syncthreads();
    if (ei_words[threadIdx.x * 2 + 1] != 0u) atomicOr(&s_any, 1);
    __syncthreads();
    int is64 = s_any ? 0 : 1;
    if (blockIdx.x == 0 && threadIdx.x == 0) g_is64 = is64;

    int i = blockIdx.x * blockDim.x + threadIdx.x;
    if (i >= batch * 2) return;
    int b = i >> 1;
    int c = (i & 1) * 2;                        // sample columns 0 and 2
    int node = ld_idx(sample, (size_t)b * 3 + c, is64);
    if (atomicCAS(&g_slot[node], 0, 1) == 0) {  // unique claimer assigns slot
        int s = atomicAdd(&g_n_needed, 1);
        g_needed_nodes[s] = node;
        atomicOr(&g_bits[node >> 5], 1u << (node & 31));
        g_slot[node] = s + 2;
    }
}

// ============ 2) k_scan: 16 edges/thread, MLP-4 dst loads ==================
__global__ void __launch_bounds__(256)
k_scan(const void* __restrict__ edge_index,
       const void* __restrict__ edge_type,
       const float* __restrict__ x,
       int n_edge, int n_rel) {
    const int is64 = g_is64;
    const int t = blockIdx.x * 256 + threadIdx.x;
    const int e0 = t * EPT;
    if (e0 >= n_edge) return;
    const int n = (e0 + EPT <= n_edge) ? EPT : (n_edge - e0);

    int dst[EPT];
    if (n == EPT) {
        if (!is64) {
            // 4 independent 16B loads in flight (MLP=4)
            const int4* p = (const int4*)((const int*)edge_index + (size_t)n_edge + e0);
            int4 v0 = p[0], v1 = p[1], v2 = p[2], v3 = p[3];
            dst[0]=v0.x; dst[1]=v0.y; dst[2]=v0.z; dst[3]=v0.w;
            dst[4]=v1.x; dst[5]=v1.y; dst[6]=v1.z; dst[7]=v1.w;
            dst[8]=v2.x; dst[9]=v2.y; dst[10]=v2.z; dst[11]=v2.w;
            dst[12]=v3.x; dst[13]=v3.y; dst[14]=v3.z; dst[15]=v3.w;
        } else {
            // 8 independent 16B loads (MLP=8)
            const longlong2* p = (const longlong2*)((const long long*)edge_index + (size_t)n_edge + e0);
            longlong2 w[8];
#pragma unroll
            for (int j = 0; j < 8; j++) w[j] = p[j];
#pragma unroll
            for (int j = 0; j < 8; j++) { dst[2*j] = (int)w[j].x; dst[2*j+1] = (int)w[j].y; }
        }
    } else {
        for (int k = 0; k < n; k++)
            dst[k] = ld_idx(edge_index, (size_t)n_edge + e0 + k, is64);
    }

    // 16 independent bitmap probes (tiny table; L1-resident after warmup)
    unsigned int hit = 0;
#pragma unroll
    for (int k = 0; k < EPT; k++) {
        if (k < n && ((g_bits[dst[k] >> 5] >> (dst[k] & 31)) & 1u))
            hit |= 1u << k;
    }

    while (hit) {
        int k = __ffs(hit) - 1;
        hit &= hit - 1;
        int s = g_slot[dst[k]] - 2;
        int e   = e0 + k;
        int r   = ld_idx(edge_type, e, is64);
        int src = ld_idx(edge_index, e, is64);
        atomicAdd(&g_cnt[s * n_rel + r], 1.0f);
        const float4* xs = (const float4*)(x + (size_t)src * DIM);
        float* m = &g_msg[((size_t)s * n_rel + r) * DIM];
#pragma unroll
        for (int j = 0; j < DIM / 4; j++) {
            float4 v = xs[j];
            atomicAdd(&m[4 * j + 0], v.x);
            atomicAdd(&m[4 * j + 1], v.y);
            atomicAdd(&m[4 * j + 2], v.z);
            atomicAdd(&m[4 * j + 3], v.w);
        }
    }
}

// ============ 3) k_go: gemm | barrier | out+msgzero | barrier | cleanup ====
// grid = (n_rel + 1) * 2 * GROUPS = 400 blocks of 128 threads (co-resident:
// 33 KB smem -> 6 blocks/SM -> 888 slots >= 400).
__global__ void __launch_bounds__(128)
k_go(const float* __restrict__ W_rel,
     const float* __restrict__ W_root,
     const float* __restrict__ x,
     const void* __restrict__ sample,
     const float* __restrict__ init_rel,
     float* __restrict__ out,
     int n_rel, int batch) {
    __shared__ float Ws[64 * DIM];   // one 64-col half, Ws[d * 64 + c]
    __shared__ float ms[DIM];

    const int tid  = threadIdx.x;
    const int gtid = blockIdx.x * 128 + tid;
    const int gsz  = gridDim.x * 128;
    const int nn   = g_n_needed;
    const int is64 = g_is64;

    // ---- phase 1: gemm (R8 config: GROUPS=8, 3 slot-iters/block) ----------
    {
        int idx  = blockIdx.x;
        int r    = idx % (n_rel + 1);
        int half = (idx / (n_rel + 1)) & 1;
        int sg   = idx / ((n_rel + 1) * 2);
        const float* W = (r < n_rel) ? (W_rel + (size_t)r * DIM * DIM) : W_root;
        int fbase = half * 64;

        for (int i = tid; i < 64 * DIM / 4; i += 128) {
            int d = i >> 4, c4 = i & 15;
            ((float4*)Ws)[d * 16 + c4] = *(const float4*)&W[d * DIM + fbase + c4 * 4];
        }
        __syncthreads();

        int c  = tid & 63;
        int dh = (tid >> 6) * 64;

        for (int s = sg; s < nn; s += GROUPS) {
            bool skip = false;
            float scale = 1.0f;
            if (r < n_rel) {
                float cnt = g_cnt[s * n_rel + r];     // uniform across block
                if (cnt == 0.0f) skip = true;
                else scale = 1.0f / cnt;
            }
            if (!skip) {
                if (r < n_rel)
                    ms[tid] = g_msg[((size_t)s * n_rel + r) * DIM + tid] * scale;
                else
                    ms[tid] = x[(size_t)g_needed_nodes[s] * DIM + tid];
            }
            __syncthreads();
            if (!skip) {
                float acc = 0.0f;
#pragma unroll
                for (int k = 0; k < 16; k++) {
                    int d = dh + k * 4;
                    float4 mv = *(const float4*)&ms[d];
                    acc += mv.x * Ws[(d + 0) * 64 + c];
                    acc += mv.y * Ws[(d + 1) * 64 + c];
                    acc += mv.z * Ws[(d + 2) * 64 + c];
                    acc += mv.w * Ws[(d + 3) * 64 + c];
                }
                atomicAdd(&g_agg[s * DIM + fbase + c], acc);
            }
            __syncthreads();
        }
    }
    barrier_sr(&g_cntB, &g_senseB, gridDim.x);

    // ---- phase 2: out (warp per batch row) + msg/cnt zeroing --------------
    {
        float4 z = make_float4(0.f, 0.f, 0.f, 0.f);
        int n_msg4 = nn * n_rel * (DIM / 4);
        for (int i = gtid; i < n_msg4; i += gsz) ((float4*)g_msg)[i] = z;
        int n_cnt = nn * n_rel;
        for (int i = gtid; i < n_cnt; i += gsz) g_cnt[i] = 0.0f;

        int lane  = tid & 31;
        int warps = gsz >> 5;
        for (int w = gtid >> 5; w < batch; w += warps) {
            int sh = 0, st = 0, rel = 0;
            if (lane == 0) {
                int h = ld_idx(sample, (size_t)w * 3 + 0, is64);
                rel   = ld_idx(sample, (size_t)w * 3 + 1, is64);
                int t = ld_idx(sample, (size_t)w * 3 + 2, is64);
                sh = g_slot[h] - 2;
                st = g_slot[t] - 2;
            }
            sh  = __shfl_sync(0xffffffffu, sh, 0);
            st  = __shfl_sync(0xffffffffu, st, 0);
            rel = __shfl_sync(0xffffffffu, rel, 0);

            float4 ah = ((const float4*)g_agg)[sh * (DIM / 4) + lane];
            float4 at = ((const float4*)g_agg)[st * (DIM / 4) + lane];
            float4 rv = ((const float4*)init_rel)[rel * (DIM / 4) + lane];
            float4 o;
            o.x = ftanh(ah.x) * (rv.x * ftanh(at.x));
            o.y = ftanh(ah.y) * (rv.y * ftanh(at.y));
            o.z = ftanh(ah.z) * (rv.z * ftanh(at.z));
            o.w = ftanh(ah.w) * (rv.w * ftanh(at.w));
            ((float4*)out)[(size_t)w * (DIM / 4) + lane] = o;
        }
    }
    barrier_sr(&g_cntB, &g_senseB, gridDim.x);

    // ---- phase 3: cleanup (agg, slot, bits, counter) -----------------------
    {
        float4 z = make_float4(0.f, 0.f, 0.f, 0.f);
        int n_agg4 = nn * (DIM / 4);
        for (int i = gtid; i < n_agg4; i += gsz) ((float4*)g_agg)[i] = z;
        for (int i = gtid; i < nn; i += gsz) {
            int node = g_needed_nodes[i];
            g_slot[node] = 0;
            g_bits[node >> 5] = 0u;   // every set bit belongs to a needed node
        }
        if (gtid == 0) g_n_needed = 0;
    }
}

// ---------------- launch ----------------
extern "C" void kernel_launch(void* const* d_in, const int* in_sizes, int n_in,
                              void* d_out, int out_size) {
    const float* init_embed = (const float*)d_in[0];
    const float* init_rel   = (const float*)d_in[1];
    const float* W_rel      = (const float*)d_in[2];
    const float* W_root     = (const float*)d_in[3];
    const void*  edge_index = d_in[4];
    const void*  edge_type  = d_in[5];
    const void*  sample     = d_in[6];
    float* out = (float*)d_out;

    int n_rel  = in_sizes[1] / DIM;
    int n_edge = in_sizes[5];
    int batch  = in_sizes[6] / 3;

    k_mark<<<(batch * 2 + 255) / 256, 256>>>((const unsigned int*)edge_index,
                                             sample, batch);
    k_scan<<<(n_edge + EPT * 256 - 1) / (EPT * 256), 256>>>(edge_index, edge_type,
                                                            init_embed, n_edge, n_rel);
    k_go  <<<(n_rel + 1) * 2 * GROUPS, 128>>>(W_rel, W_root, init_embed, sample,
                                              init_rel, out, n_rel, batch);
}